// round 1
// baseline (speedup 1.0000x reference)
#include <cuda_runtime.h>
#include <cstdint>
#include <math_constants.h>

#define NMAX 100000
#define CH 64
#define BMAX 512
#define KTOP 30
#define PLEN 1950   // 30 * 65
#define SEGMAX 4096

// ---------------- scratch (static device globals; no allocs allowed) -------
__device__ float g_xw1[NMAX * CH];
__device__ float g_agg1[NMAX * CH];
__device__ float g_x1[NMAX * CH];
__device__ float g_deg[NMAX];
__device__ float g_dis[NMAX];
__device__ float g_xw2[NMAX];
__device__ float g_agg2[NMAX];
__device__ float g_x2[NMAX];
__device__ int   g_cnt[BMAX];
__device__ int   g_start[BMAX];

// ---------------- K1: xw1 = x @ W1 (100000x128 @ 128x64) -------------------
#define GEMM_TR 128
#define XPITCH 132
#define GEMM_SMEM ((GEMM_TR * XPITCH + 128 * 64) * 4)

__global__ void gemm1_kernel(const float* __restrict__ x,
                             const float* __restrict__ W, int n) {
    extern __shared__ float smem[];
    float* xs = smem;                       // [128][132]
    float* ws = smem + GEMM_TR * XPITCH;    // [128][64]
    int t = threadIdx.x;
    int row0 = blockIdx.x * GEMM_TR;

    // load W1 (8192 floats)
    for (int i = t; i < 128 * 64 / 4; i += 256)
        ((float4*)ws)[i] = ((const float4*)W)[i];
    // load x tile (128 rows x 128 cols)
    for (int i = t; i < GEMM_TR * 32; i += 256) {
        int r = i >> 5, c4 = i & 31;
        float4 v = make_float4(0.f, 0.f, 0.f, 0.f);
        if (row0 + r < n) v = ((const float4*)x)[(size_t)(row0 + r) * 32 + c4];
        *(float4*)&xs[r * XPITCH + c4 * 4] = v;
    }
    __syncthreads();

    int tx = t & 7;      // 8 col-groups of 8 cols
    int ty = t >> 3;     // 32 row-groups of 4 rows
    float acc[4][8];
#pragma unroll
    for (int i = 0; i < 4; i++)
#pragma unroll
        for (int j = 0; j < 8; j++) acc[i][j] = 0.f;

#pragma unroll 4
    for (int k = 0; k < 128; k++) {
        float4 b0 = *(float4*)&ws[k * 64 + tx * 8];
        float4 b1 = *(float4*)&ws[k * 64 + tx * 8 + 4];
        float a0 = xs[(ty * 4 + 0) * XPITCH + k];
        float a1 = xs[(ty * 4 + 1) * XPITCH + k];
        float a2 = xs[(ty * 4 + 2) * XPITCH + k];
        float a3 = xs[(ty * 4 + 3) * XPITCH + k];
        float bb[8] = {b0.x, b0.y, b0.z, b0.w, b1.x, b1.y, b1.z, b1.w};
        float aa[4] = {a0, a1, a2, a3};
#pragma unroll
        for (int i = 0; i < 4; i++)
#pragma unroll
            for (int j = 0; j < 8; j++) acc[i][j] += aa[i] * bb[j];
    }

#pragma unroll
    for (int i = 0; i < 4; i++) {
        int r = row0 + ty * 4 + i;
        if (r < n) {
            float4 o0 = make_float4(acc[i][0], acc[i][1], acc[i][2], acc[i][3]);
            float4 o1 = make_float4(acc[i][4], acc[i][5], acc[i][6], acc[i][7]);
            *(float4*)&g_xw1[(size_t)r * 64 + tx * 8] = o0;
            *(float4*)&g_xw1[(size_t)r * 64 + tx * 8 + 4] = o1;
        }
    }
}

// ---------------- K2: degree counts over edges ------------------------------
__global__ void deg_kernel(const int* __restrict__ row,
                           const int* __restrict__ col, int E) {
    int e = blockIdx.x * blockDim.x + threadIdx.x;
    if (e >= E) return;
    int r = row[e], c = col[e];
    if (r != c) atomicAdd(&g_deg[c], 1.0f);
}

// ---------------- K3: dis = rsqrt(deg + 1) ----------------------------------
__global__ void dis_kernel(int n) {
    int i = blockIdx.x * blockDim.x + threadIdx.x;
    if (i < n) g_dis[i] = rsqrtf(g_deg[i] + 1.0f);
}

// ---------------- K4: edge aggregation for conv1 (64 ch, float4 red) --------
__global__ void agg1_kernel(const int* __restrict__ row,
                            const int* __restrict__ col, int E) {
    int t = blockIdx.x * blockDim.x + threadIdx.x;
    int e = t >> 4;
    int sub = t & 15;
    if (e >= E) return;
    int r = __ldg(row + e), c = __ldg(col + e);
    if (r == c) return;
    float cf = g_dis[r] * g_dis[c];
    float4 v = *(const float4*)&g_xw1[(size_t)r * 64 + sub * 4];
    v.x *= cf; v.y *= cf; v.z *= cf; v.w *= cf;
    atomicAdd((float4*)&g_agg1[(size_t)c * 64 + sub * 4], v);  // sm_90+ 128b RED
}

// ---------------- K5: x1 = tanh(agg1 + xw1*dis^2 + b1); xw2 = x1 . W2 -------
__global__ void node1_kernel(const float* __restrict__ W2,
                             const float* __restrict__ b1, int n) {
    int gt = blockIdx.x * blockDim.x + threadIdx.x;
    int node = gt >> 5;
    int lane = gt & 31;
    if (node >= n) return;
    float d2 = g_dis[node]; d2 = d2 * d2;
    size_t base = (size_t)node * 64 + lane * 2;
    float2 xw = *(const float2*)&g_xw1[base];
    float2 ag = *(const float2*)&g_agg1[base];
    float2 bb = *(const float2*)&b1[lane * 2];
    float v0 = tanhf(ag.x + xw.x * d2 + bb.x);
    float v1 = tanhf(ag.y + xw.y * d2 + bb.y);
    *(float2*)&g_x1[base] = make_float2(v0, v1);
    float2 w2 = *(const float2*)&W2[lane * 2];
    float dot = v0 * w2.x + v1 * w2.y;
#pragma unroll
    for (int off = 16; off; off >>= 1) dot += __shfl_xor_sync(~0u, dot, off);
    if (lane == 0) g_xw2[node] = dot;
}

// ---------------- K6: edge aggregation for conv2 (scalar) -------------------
__global__ void agg2_kernel(const int* __restrict__ row,
                            const int* __restrict__ col, int E) {
    int e = blockIdx.x * blockDim.x + threadIdx.x;
    if (e >= E) return;
    int r = row[e], c = col[e];
    if (r == c) return;
    float v = g_xw2[r] * g_dis[r] * g_dis[c];
    atomicAdd(&g_agg2[c], v);
}

// ---------------- K7: x2 = tanh(...); graph node counts ---------------------
__global__ void node2_kernel(const float* __restrict__ b2,
                             const int* __restrict__ batch, int n) {
    int i = blockIdx.x * blockDim.x + threadIdx.x;
    if (i >= n) return;
    float d2 = g_dis[i]; d2 = d2 * d2;
    g_x2[i] = tanhf(g_agg2[i] + g_xw2[i] * d2 + b2[0]);
    atomicAdd(&g_cnt[batch[i]], 1);
}

// ---------------- K8: exclusive scan of counts -> segment starts ------------
__global__ void scan_kernel(int B) {
    __shared__ int s[BMAX];
    int t = threadIdx.x;
    int v = (t < B) ? g_cnt[t] : 0;
    s[t] = v;
    __syncthreads();
    for (int off = 1; off < BMAX; off <<= 1) {
        int u = (t >= off) ? s[t - off] : 0;
        __syncthreads();
        s[t] += u;
        __syncthreads();
    }
    if (t < B) g_start[t] = s[t] - v;
}

// ---------------- K9: fused sort-pool(top-30) + CNN head + MLP + logsoftmax -
__global__ void head_kernel(const float* __restrict__ w3, const float* __restrict__ b3,
                            const float* __restrict__ w4, const float* __restrict__ b4,
                            const float* __restrict__ fw1, const float* __restrict__ fb1,
                            const float* __restrict__ fw2, const float* __restrict__ fb2,
                            float* __restrict__ out, int B) {
    __shared__ float sc[SEGMAX];
    __shared__ int sel[KTOP];
    __shared__ float p[PLEN];
    __shared__ float c3[320];
    __shared__ float pl[160];
    __shared__ float h[192];
    __shared__ float ll[128];
    __shared__ float o[18];
    __shared__ unsigned long long redk[256];

    int g = blockIdx.x;
    int t = threadIdx.x;
    int start = g_start[g];
    int cnt = min(g_cnt[g], SEGMAX);
    int ksel = min(cnt, KTOP);

    for (int i = t; i < cnt; i += 256) sc[i] = g_x2[start + i];
    __syncthreads();

    // iterative stable top-K: max score, tie -> lowest index (matches lexsort)
    for (int j = 0; j < ksel; j++) {
        unsigned long long best = 0ull;
        for (int i = t; i < cnt; i += 256) {
            unsigned u = __float_as_uint(sc[i]);
            u = (u & 0x80000000u) ? ~u : (u | 0x80000000u);
            unsigned long long key =
                ((unsigned long long)u << 32) | (unsigned)(~i);
            if (key > best) best = key;
        }
        redk[t] = best;
        __syncthreads();
        for (int off = 128; off; off >>= 1) {
            if (t < off) redk[t] = max(redk[t], redk[t + off]);
            __syncthreads();
        }
        int pos = (int)(~(unsigned)(redk[0] & 0xFFFFFFFFull));
        if (t == 0) {
            sel[j] = start + pos;
            sc[pos] = -CUDART_INF_F;
        }
        __syncthreads();
    }

    // build pooled row p[30*65], zero-padded
    for (int idx = t; idx < PLEN; idx += 256) {
        int j = idx / 65, c = idx % 65;
        float v = 0.f;
        if (j < ksel) {
            int node = sel[j];
            v = (c < 64) ? g_x1[(size_t)node * 64 + c] : g_x2[node];
        }
        p[idx] = v;
    }
    __syncthreads();

    // conv3: 16 out-ch, kernel 97, stride 97 -> length 20, relu
    for (int idx = t; idx < 320; idx += 256) {
        int oc = idx / 20, tt = idx % 20;
        float s = b3[oc];
        const float* w = w3 + oc * 97;
        const float* pp = p + tt * 97;
#pragma unroll 1
        for (int i = 0; i < 97; i++) s += pp[i] * w[i];
        c3[oc * 20 + tt] = fmaxf(s, 0.f);
    }
    __syncthreads();

    // maxpool k=2 s=2 -> length 10
    for (int idx = t; idx < 160; idx += 256) {
        int oc = idx / 10, tt = idx % 10;
        pl[idx] = fmaxf(c3[oc * 20 + 2 * tt], c3[oc * 20 + 2 * tt + 1]);
    }
    __syncthreads();

    // conv4: 32 out-ch, 16 in-ch, kernel 5, stride 1 -> length 6, relu
    for (int idx = t; idx < 192; idx += 256) {
        int oc = idx / 6, tt = idx % 6;
        float s = b4[oc];
#pragma unroll
        for (int ic = 0; ic < 16; ic++)
#pragma unroll
            for (int i = 0; i < 5; i++)
                s += pl[ic * 10 + tt + i] * w4[oc * 80 + ic * 5 + i];
        h[idx] = fmaxf(s, 0.f);
    }
    __syncthreads();

    // fc1 (192->128) + relu, write last_layer
    for (int j = t; j < 128; j += 256) {
        float s = fb1[j];
#pragma unroll 4
        for (int i = 0; i < 192; i++) s += h[i] * fw1[i * 128 + j];
        float r = fmaxf(s, 0.f);
        ll[j] = r;
        out[(size_t)2 * B * 18 + (size_t)g * 128 + j] = r;
    }
    __syncthreads();

    // fc2 (128->18), write out
    for (int j = t; j < 18; j += 256) {
        float s = fb2[j];
#pragma unroll 4
        for (int i = 0; i < 128; i++) s += ll[i] * fw2[i * 18 + j];
        o[j] = s;
        out[(size_t)B * 18 + (size_t)g * 18 + j] = s;
    }
    __syncthreads();

    // log_softmax, write classes
    if (t == 0) {
        float m = o[0];
        for (int j = 1; j < 18; j++) m = fmaxf(m, o[j]);
        float se = 0.f;
        for (int j = 0; j < 18; j++) se += expf(o[j] - m);
        float lse = logf(se) + m;
        for (int j = 0; j < 18; j++) out[(size_t)g * 18 + j] = o[j] - lse;
    }
}

// ---------------- launch ----------------------------------------------------
extern "C" void kernel_launch(void* const* d_in, const int* in_sizes, int n_in,
                              void* d_out, int out_size) {
    const float* x    = (const float*)d_in[0];
    const int* ei     = (const int*)d_in[1];
    const int* batch  = (const int*)d_in[2];
    const float* W1   = (const float*)d_in[4];
    const float* b1   = (const float*)d_in[5];
    const float* W2   = (const float*)d_in[6];
    const float* b2   = (const float*)d_in[7];
    const float* w3   = (const float*)d_in[8];
    const float* b3   = (const float*)d_in[9];
    const float* w4   = (const float*)d_in[10];
    const float* b4   = (const float*)d_in[11];
    const float* fw1  = (const float*)d_in[12];
    const float* fb1  = (const float*)d_in[13];
    const float* fw2  = (const float*)d_in[14];
    const float* fb2  = (const float*)d_in[15];
    float* out = (float*)d_out;

    int n = in_sizes[0] / 128;
    int E = in_sizes[1] / 2;
    int B = out_size / 164;   // 18 + 18 + 128
    const int* row = ei;
    const int* col = ei + E;

    void* pa;
    cudaGetSymbolAddress(&pa, g_agg1);
    cudaMemsetAsync(pa, 0, (size_t)n * 64 * sizeof(float), 0);
    cudaGetSymbolAddress(&pa, g_agg2);
    cudaMemsetAsync(pa, 0, (size_t)n * sizeof(float), 0);
    cudaGetSymbolAddress(&pa, g_deg);
    cudaMemsetAsync(pa, 0, (size_t)n * sizeof(float), 0);
    cudaGetSymbolAddress(&pa, g_cnt);
    cudaMemsetAsync(pa, 0, (size_t)B * sizeof(int), 0);

    cudaFuncSetAttribute(gemm1_kernel,
                         cudaFuncAttributeMaxDynamicSharedMemorySize, GEMM_SMEM);
    gemm1_kernel<<<(n + GEMM_TR - 1) / GEMM_TR, 256, GEMM_SMEM>>>(x, W1, n);

    deg_kernel<<<(E + 255) / 256, 256>>>(row, col, E);
    dis_kernel<<<(n + 255) / 256, 256>>>(n);

    {
        long long tot = (long long)E * 16;
        int blocks = (int)((tot + 255) / 256);
        agg1_kernel<<<blocks, 256>>>(row, col, E);
    }

    node1_kernel<<<(n * 32 + 255) / 256, 256>>>(W2, b1, n);
    agg2_kernel<<<(E + 255) / 256, 256>>>(row, col, E);
    node2_kernel<<<(n + 255) / 256, 256>>>(b2, batch, n);
    scan_kernel<<<1, BMAX>>>(B);
    head_kernel<<<B, 256>>>(w3, b3, w4, b4, fw1, fb1, fw2, fb2, out, B);
}